// round 1
// baseline (speedup 1.0000x reference)
#include <cuda_runtime.h>
#include <math.h>
#include <stdint.h>

#define NLVL 16
#define NPTS (1 << 21)
#define TPB  256

// Per-level constants, computed on host each launch with the SAME libm ops the
// Python reference uses (log2/pow/ceil on this host's glibc) so RES/OFFS match
// bit-exactly even where ceil() sits on an integer boundary (levels 0..4).
struct LP {
    float rm1[NLVL];    // (float)(res - 1)
    int   res[NLVL];
    int   offs[NLVL];   // entry offset of level l in table
    int   dense[NLVL];  // 1 if hsize >= res*res (direct index), else hash
};

__global__ void __launch_bounds__(TPB) hashenc_kernel(
    const float2* __restrict__ xy,
    const float2* __restrict__ tab,
    float2*       __restrict__ out,
    const LP lp)
{
    // Stage level constants in smem: lvl = tid&15 is a divergent index; smem
    // handles divergent reads via broadcast/banking, constant bank would replay.
    __shared__ float s_rm1[NLVL];
    __shared__ int   s_res[NLVL], s_off[NLVL], s_dense[NLVL];
    if (threadIdx.x < NLVL) {
        int t = threadIdx.x;
        s_rm1[t]   = lp.rm1[t];
        s_res[t]   = lp.res[t];
        s_off[t]   = lp.offs[t];
        s_dense[t] = lp.dense[t];
    }
    __syncthreads();

    unsigned tid   = blockIdx.x * TPB + threadIdx.x;
    unsigned point = tid >> 4;
    unsigned lvl   = tid & 15u;

    float2 p  = __ldg(&xy[point]);     // 16 lanes share one point: 2 lines/warp
    float rm1 = s_rm1[lvl];
    int   res = s_res[lvl];
    int   off = s_off[lvl];
    int   dns = s_dense[lvl];

    float px = fmaf(p.x, rm1, 0.5f);
    float py = fmaf(p.y, rm1, 0.5f);
    float fx = floorf(px), fy = floorf(py);
    float wx = px - fx,    wy = py - fy;
    int   gx = (int)fx,    gy = (int)fy;

    int i00, i10, i01, i11;
    if (dns) {
        int b = gx + gy * res;
        i00 = b;        i10 = b + 1;
        i01 = b + res;  i11 = b + res + 1;
    } else {
        // hashed levels always have hsize == 2^19 (LOG2_T), so % == &
        const unsigned M  = (1u << 19) - 1u;
        unsigned h0 = (unsigned)gy       * 2654435761u;
        unsigned h1 = (unsigned)(gy + 1) * 2654435761u;
        i00 = (int)(((unsigned)gx       ^ h0) & M);
        i10 = (int)(((unsigned)(gx + 1) ^ h0) & M);
        i01 = (int)(((unsigned)gx       ^ h1) & M);
        i11 = (int)(((unsigned)(gx + 1) ^ h1) & M);
    }

    const float2* t = tab + off;
    float2 f00 = __ldg(t + i00);
    float2 f10 = __ldg(t + i10);
    float2 f01 = __ldg(t + i01);
    float2 f11 = __ldg(t + i11);

    float ux = 1.0f - wx, uy = 1.0f - wy;
    float w00 = ux * uy, w10 = wx * uy, w01 = ux * wy, w11 = wx * wy;

    float ox = f00.x * w00 + f10.x * w10 + f01.x * w01 + f11.x * w11;
    float oy = f00.y * w00 + f10.y * w10 + f01.y * w01 + f11.y * w11;

    // out layout: (point, 32 floats) = (point, 16 float2) -> index == tid
    out[tid] = make_float2(ox, oy);
}

extern "C" void kernel_launch(void* const* d_in, const int* in_sizes, int n_in,
                              void* d_out, int out_size)
{
    (void)in_sizes; (void)n_in; (void)out_size;

    // Mirror the reference's level-geometry computation exactly (same libm).
    LP lp;
    long long sizes[NLVL];
    int       resv [NLVL];
    double log2s = log2(1.5);
    long long off = 0;
    for (int l = 0; l < NLVL; l++) {
        double scale = pow(2.0, (double)l * log2s) * 16.0 - 1.0;
        int r = (int)ceil(scale) + 1;
        long long sz = (((long long)r * (long long)r + 7) / 8) * 8;
        if (sz > (1LL << 19)) sz = (1LL << 19);
        resv[l]    = r;
        sizes[l]   = sz;
        lp.rm1[l]  = (float)(r - 1);
        lp.res[l]  = r;
        lp.offs[l] = (int)off;
        off += sz;
    }
    for (int l = 0; l < NLVL; l++)
        lp.dense[l] = (sizes[l] >= (long long)resv[l] * resv[l]) ? 1 : 0;

    const float2* xy  = (const float2*)d_in[0];
    const float2* tab = (const float2*)d_in[1];
    float2*       out = (float2*)d_out;

    unsigned total  = (unsigned)NPTS * NLVL;     // 33,554,432 threads
    unsigned blocks = total / TPB;               // 131,072 blocks

    hashenc_kernel<<<blocks, TPB>>>(xy, tab, out, lp);
}

// round 2
// speedup vs baseline: 1.1719x; 1.1719x over previous
#include <cuda_runtime.h>
#include <math.h>
#include <stdint.h>

#define NLVL 16
#define NPTS (1 << 21)
#define TPB  256

// Per-level constants, computed on host each launch with the SAME libm ops the
// Python reference uses so RES/OFFS match bit-exactly.
struct LP {
    float rm1[NLVL];    // (float)(res - 1)
    int   res[NLVL];
    int   offs[NLVL];   // entry offset of level l in table
    int   dense[NLVL];  // 1 if hsize >= res*res (direct index), else hash
};

__global__ void __launch_bounds__(TPB) hashenc_kernel(
    const float2* __restrict__ xy,
    const float2* __restrict__ tab,
    float2*       __restrict__ out,
    const LP lp)
{
    __shared__ float s_rm1[NLVL];
    __shared__ int   s_res[NLVL], s_off[NLVL], s_dense[NLVL];
    if (threadIdx.x < NLVL) {
        int t = threadIdx.x;
        s_rm1[t]   = lp.rm1[t];
        s_res[t]   = lp.res[t];
        s_off[t]   = lp.offs[t];
        s_dense[t] = lp.dense[t];
    }
    __syncthreads();

    unsigned tid   = blockIdx.x * TPB + threadIdx.x;
    unsigned point = tid >> 4;
    unsigned lvl   = tid & 15u;

    float2 p  = __ldg(&xy[point]);
    float rm1 = s_rm1[lvl];
    int   res = s_res[lvl];
    int   off = s_off[lvl];
    int   dns = s_dense[lvl];

    float px = fmaf(p.x, rm1, 0.5f);
    float py = fmaf(p.y, rm1, 0.5f);
    float fx = floorf(px), fy = floorf(py);
    float wx = px - fx,    wy = py - fy;
    int   gx = (int)fx,    gy = (int)fy;

    int i00, i10, i01, i11;
    if (dns) {
        int b = gx + gy * res;
        i00 = b;        i10 = b + 1;
        i01 = b + res;  i11 = b + res + 1;
    } else {
        const unsigned M  = (1u << 19) - 1u;   // hashed hsize is always 2^19
        unsigned h0 = (unsigned)gy       * 2654435761u;
        unsigned h1 = (unsigned)(gy + 1) * 2654435761u;
        i00 = (int)(((unsigned)gx       ^ h0) & M);
        i10 = (int)(((unsigned)(gx + 1) ^ h0) & M);
        i01 = (int)(((unsigned)gx       ^ h1) & M);
        i11 = (int)(((unsigned)(gx + 1) ^ h1) & M);
    }

    const float2* t  = tab + off;           // 64B aligned (off multiple of 8)
    const float4* t4 = (const float4*)t;

    float2 f00, f10, f01, f11;

    // Row y0: if the two x-corners form an aligned entry pair {2k, 2k+1},
    // fetch both with ONE 16B load (1 wavefront + 1 L2 sector instead of 2+2).
    // Dense: true iff i00 even. Hashed: true iff gx even (i10 == i00^1 then).
    if (i10 == (i00 ^ 1)) {
        float4 r = __ldg(t4 + (i00 >> 1));
        if (i00 & 1) { f00 = make_float2(r.z, r.w); f10 = make_float2(r.x, r.y); }
        else         { f00 = make_float2(r.x, r.y); f10 = make_float2(r.z, r.w); }
    } else {
        f00 = __ldg(t + i00);
        f10 = __ldg(t + i10);
    }

    // Row y1: same trick.
    if (i11 == (i01 ^ 1)) {
        float4 r = __ldg(t4 + (i01 >> 1));
        if (i01 & 1) { f01 = make_float2(r.z, r.w); f11 = make_float2(r.x, r.y); }
        else         { f01 = make_float2(r.x, r.y); f11 = make_float2(r.z, r.w); }
    } else {
        f01 = __ldg(t + i01);
        f11 = __ldg(t + i11);
    }

    float ux = 1.0f - wx, uy = 1.0f - wy;
    float w00 = ux * uy, w10 = wx * uy, w01 = ux * wy, w11 = wx * wy;

    float ox = f00.x * w00 + f10.x * w10 + f01.x * w01 + f11.x * w11;
    float oy = f00.y * w00 + f10.y * w10 + f01.y * w01 + f11.y * w11;

    out[tid] = make_float2(ox, oy);
}

extern "C" void kernel_launch(void* const* d_in, const int* in_sizes, int n_in,
                              void* d_out, int out_size)
{
    (void)in_sizes; (void)n_in; (void)out_size;

    LP lp;
    long long sizes[NLVL];
    int       resv [NLVL];
    double log2s = log2(1.5);
    long long off = 0;
    for (int l = 0; l < NLVL; l++) {
        double scale = pow(2.0, (double)l * log2s) * 16.0 - 1.0;
        int r = (int)ceil(scale) + 1;
        long long sz = (((long long)r * (long long)r + 7) / 8) * 8;
        if (sz > (1LL << 19)) sz = (1LL << 19);
        resv[l]    = r;
        sizes[l]   = sz;
        lp.rm1[l]  = (float)(r - 1);
        lp.res[l]  = r;
        lp.offs[l] = (int)off;
        off += sz;
    }
    for (int l = 0; l < NLVL; l++)
        lp.dense[l] = (sizes[l] >= (long long)resv[l] * resv[l]) ? 1 : 0;

    const float2* xy  = (const float2*)d_in[0];
    const float2* tab = (const float2*)d_in[1];
    float2*       out = (float2*)d_out;

    unsigned total  = (unsigned)NPTS * NLVL;
    unsigned blocks = total / TPB;

    hashenc_kernel<<<blocks, TPB>>>(xy, tab, out, lp);
}